// round 11
// baseline (speedup 1.0000x reference)
#include <cuda_runtime.h>

// 2x2 non-overlapping max pool, fp32.
// Input : (16, 64, 512, 512) flattened as (IMG=1024, 512, 512)
// Output: (16, 64, 256, 256) flattened as (IMG=1024, 256, 256)
//
// R10 (ninth resubmit; rounds 2-10 all hit broker acquisition timeouts):
// each thread produces TWO output float4s, located half-the-tensor apart, so
// every LDG.128 / STG.128 remains perfectly coalesced within the warp while
// per-thread MLP rises from 4 to 8 front-batched loads. Streaming cache hints
// (__ldcs / __stcs) mark the zero-reuse streams evict-first.

#define IMG   1024      // 16 * 64
#define H     512
#define W     512
#define OH    256
#define OW    256

#define OV_PER_ROW 64                        // float4 outputs per output row
#define TOTAL_V4   (IMG * OH * OV_PER_ROW)   // 16,777,216
#define HALF_V4    (TOTAL_V4 / 2)            // 8,388,608

__device__ __forceinline__ float4 pool_combine(float4 a0, float4 a1,
                                               float4 b0, float4 b1)
{
    float4 o;
    o.x = fmaxf(fmaxf(a0.x, a0.y), fmaxf(b0.x, b0.y));
    o.y = fmaxf(fmaxf(a0.z, a0.w), fmaxf(b0.z, b0.w));
    o.z = fmaxf(fmaxf(a1.x, a1.y), fmaxf(b1.x, b1.y));
    o.w = fmaxf(fmaxf(a1.z, a1.w), fmaxf(b1.z, b1.w));
    return o;
}

__global__ __launch_bounds__(256) void maxpool2x2_kernel(
    const float* __restrict__ in, float* __restrict__ out)
{
    int t0 = blockIdx.x * blockDim.x + threadIdx.x;   // < HALF_V4 (exact grid)
    int t1 = t0 + HALF_V4;

    // ---- decompose both output-vector indices ----
    int ovec0 = t0 & (OV_PER_ROW - 1);
    int rest0 = t0 >> 6;
    int orow0 = rest0 & (OH - 1);
    int img0  = rest0 >> 8;

    int ovec1 = t1 & (OV_PER_ROW - 1);
    int rest1 = t1 >> 6;
    int orow1 = rest1 & (OH - 1);
    int img1  = rest1 >> 8;

    const float4* r0a = (const float4*)(in + (size_t)img0 * (H * W)
                                           + (size_t)(2 * orow0) * W + 8 * ovec0);
    const float4* r0b = (const float4*)((const float*)r0a + W);
    const float4* r1a = (const float4*)(in + (size_t)img1 * (H * W)
                                           + (size_t)(2 * orow1) * W + 8 * ovec1);
    const float4* r1b = (const float4*)((const float*)r1a + W);

    // ---- front-batched loads: 8 independent LDG.128 (MLP=8), streaming ----
    float4 a0 = __ldcs(&r0a[0]);
    float4 a1 = __ldcs(&r0a[1]);
    float4 b0 = __ldcs(&r0b[0]);
    float4 b1 = __ldcs(&r0b[1]);
    float4 c0 = __ldcs(&r1a[0]);
    float4 c1 = __ldcs(&r1a[1]);
    float4 d0 = __ldcs(&r1b[0]);
    float4 d1 = __ldcs(&r1b[1]);

    float4 o0 = pool_combine(a0, a1, b0, b1);
    float4 o1 = pool_combine(c0, c1, d0, d1);

    __stcs((float4*)(out + (size_t)img0 * (OH * OW) + (size_t)orow0 * OW + 4 * ovec0), o0);
    __stcs((float4*)(out + (size_t)img1 * (OH * OW) + (size_t)orow1 * OW + 4 * ovec1), o1);
}

extern "C" void kernel_launch(void* const* d_in, const int* in_sizes, int n_in,
                              void* d_out, int out_size)
{
    const float* in  = (const float*)d_in[0];
    float*       out = (float*)d_out;

    // HALF_V4 = 8,388,608 threads; 256 threads/block -> 32,768 blocks (exact)
    maxpool2x2_kernel<<<HALF_V4 / 256, 256>>>(in, out);
}